// round 11
// baseline (speedup 1.0000x reference)
#include <cuda_runtime.h>
#include <math.h>
#include <float.h>

#define Tn   512
#define Bn   64
#define En   256
#define Hn   512
#define G4   2048
#define NBLK 128
#define NTHR 256

// Scratch (device globals: the sanctioned alloc-free scratch mechanism)
__device__ float    g_xg[(size_t)Tn * G4 * Bn];  // [t][j][b]  256 MB
__device__ float    g_h[2][Hn * Bn];             // ping-pong, [hidx][b]
__device__ float    g_feat[Hn * Bn];             // [hidx][b]
__device__ unsigned g_count;                     // barrier arrivals (self-resetting)
__device__ unsigned g_gen;                       // barrier generation (free-running)

// ---------------------------------------------------------------------------
// Scoped memory ops (cross-SM data traffic is L2-scoped: STG + bulk-copy reads,
// so gpu-scope acquire/release suffices — no full MEMBAR / L1 flush needed).
// ---------------------------------------------------------------------------
__device__ __forceinline__ unsigned ld_relaxed_gpu(const unsigned* p) {
    unsigned v;
    asm volatile("ld.relaxed.gpu.global.u32 %0, [%1];" : "=r"(v) : "l"(p));
    return v;
}
__device__ __forceinline__ unsigned ld_acquire_gpu(const unsigned* p) {
    unsigned v;
    asm volatile("ld.acquire.gpu.global.u32 %0, [%1];" : "=r"(v) : "l"(p));
    return v;
}
__device__ __forceinline__ unsigned atom_add_release_gpu(unsigned* p, unsigned v) {
    unsigned old;
    asm volatile("atom.add.release.gpu.global.u32 %0, [%1], %2;"
                 : "=r"(old) : "l"(p), "r"(v));
    return old;
}
__device__ __forceinline__ void st_relaxed_gpu(unsigned* p, unsigned v) {
    asm volatile("st.relaxed.gpu.global.u32 [%0], %1;" :: "l"(p), "r"(v));
}
__device__ __forceinline__ void st_release_gpu(unsigned* p, unsigned v) {
    asm volatile("st.release.gpu.global.u32 [%0], %1;" :: "l"(p), "r"(v));
}

// ---- bulk async copy (1D, global->shared::cta) + mbarrier ------------------
__device__ __forceinline__ void bulk_g2s(void* smem_dst, const void* gmem_src,
                                         unsigned bytes, void* mbar) {
    unsigned d = (unsigned)__cvta_generic_to_shared(smem_dst);
    unsigned m = (unsigned)__cvta_generic_to_shared(mbar);
    asm volatile(
        "cp.async.bulk.shared::cta.global.mbarrier::complete_tx::bytes "
        "[%0], [%1], %2, [%3];"
        :: "r"(d), "l"(gmem_src), "r"(bytes), "r"(m) : "memory");
}
__device__ __forceinline__ void mbar_init(void* mbar, unsigned cnt) {
    unsigned m = (unsigned)__cvta_generic_to_shared(mbar);
    asm volatile("mbarrier.init.shared::cta.b64 [%0], %1;" :: "r"(m), "r"(cnt)
                 : "memory");
}
__device__ __forceinline__ void mbar_expect_tx(void* mbar, unsigned bytes) {
    unsigned m = (unsigned)__cvta_generic_to_shared(mbar);
    asm volatile("mbarrier.arrive.expect_tx.shared::cta.b64 _, [%0], %1;"
                 :: "r"(m), "r"(bytes) : "memory");
}
__device__ __forceinline__ void mbar_wait_parity(void* mbar, unsigned parity) {
    unsigned m = (unsigned)__cvta_generic_to_shared(mbar);
    asm volatile(
        "{\n\t"
        ".reg .pred P;\n\t"
        "WAIT_%=:\n\t"
        "mbarrier.try_wait.parity.acquire.cta.shared::cta.b64 P, [%0], %1;\n\t"
        "@P bra.uni DONE_%=;\n\t"
        "bra.uni WAIT_%=;\n\t"
        "DONE_%=:\n\t"
        "}"
        :: "r"(m), "r"(parity) : "memory");
}
__device__ __forceinline__ void fence_proxy_async_f() {
    asm volatile("fence.proxy.async;" ::: "memory");
}

// Packed fp32x2 FMA (exact fp32 semantics).
__device__ __forceinline__ unsigned long long ffma2(unsigned long long a,
                                                    unsigned long long b,
                                                    unsigned long long c) {
    unsigned long long d;
    asm("fma.rn.f32x2 %0, %1, %2, %3;" : "=l"(d) : "l"(a), "l"(b), "l"(c));
    return d;
}

// Fast, accurate-enough transcendentals (MUFU-based, ~1e-7 rel err).
__device__ __forceinline__ float sigf(float x) {
    return 1.f / (1.f + __expf(-x));
}
__device__ __forceinline__ float tanhf_fast(float x) {
    return 2.f / (1.f + __expf(-2.f * x)) - 1.f;
}

// ---------------------------------------------------------------------------
// Grid-wide generation barrier (all NBLK blocks co-resident).
// ---------------------------------------------------------------------------
__device__ __forceinline__ void grid_barrier() {
    __syncthreads();
    if (threadIdx.x == 0) {
        const unsigned cur = ld_relaxed_gpu(&g_gen);
        if (atom_add_release_gpu(&g_count, 1u) == NBLK - 1) {
            st_relaxed_gpu(&g_count, 0u);
            st_release_gpu(&g_gen, cur + 1u);   // release orders the reset too
        } else {
            while (ld_acquire_gpu(&g_gen) == cur) {}
        }
    }
    __syncthreads();
}

// ---------------------------------------------------------------------------
// Kernel 1: fused embedding gather + input projection GEMM (unchanged).
// ---------------------------------------------------------------------------
__global__ __launch_bounds__(256)
void embed_gemm_kernel(const int*   __restrict__ x,
                       const float* __restrict__ emb,
                       const float* __restrict__ Wih,
                       const float* __restrict__ bih,
                       const float* __restrict__ bhh) {
    __shared__ float sW[32][132];   // [k][j], pad keeps float4 alignment
    __shared__ float sE[32][68];    // [k][b]
    __shared__ int   sTok[Bn];

    const int tid   = threadIdx.x;
    const int jBase = blockIdx.x * 128;
    const int t     = blockIdx.y;

    if (tid < Bn) sTok[tid] = x[tid * Tn + t];
    __syncthreads();

    const int tb = tid & 15;    // b-group (4 batches)
    const int tj = tid >> 4;    // j-group (8 rows)

    float acc[8][4];
#pragma unroll
    for (int jj = 0; jj < 8; ++jj)
#pragma unroll
        for (int bb = 0; bb < 4; ++bb) acc[jj][bb] = 0.f;

    for (int kc = 0; kc < En; kc += 32) {
#pragma unroll
        for (int i = 0; i < 16; ++i) {                 // 128x32 W chunk
            int idx = tid + i * 256;
            int k = idx & 31, j = idx >> 5;
            sW[k][j] = Wih[(size_t)(jBase + j) * En + kc + k];
        }
#pragma unroll
        for (int i = 0; i < 8; ++i) {                  // 64x32 emb chunk (gathered)
            int idx = tid + i * 256;
            int k = idx & 31, b = idx >> 5;
            sE[k][b] = emb[(size_t)sTok[b] * En + kc + k];
        }
        __syncthreads();

#pragma unroll
        for (int k = 0; k < 32; ++k) {
            const float4 ev = *reinterpret_cast<const float4*>(&sE[k][tb * 4]);
            const float4 wa = *reinterpret_cast<const float4*>(&sW[k][tj * 8]);
            const float4 wb = *reinterpret_cast<const float4*>(&sW[k][tj * 8 + 4]);
            const float e4[4] = {ev.x, ev.y, ev.z, ev.w};
            const float w8[8] = {wa.x, wa.y, wa.z, wa.w, wb.x, wb.y, wb.z, wb.w};
#pragma unroll
            for (int jj = 0; jj < 8; ++jj)
#pragma unroll
                for (int bb = 0; bb < 4; ++bb)
                    acc[jj][bb] += w8[jj] * e4[bb];
        }
        __syncthreads();
    }

    float* xg_t = g_xg + (size_t)t * (G4 * Bn);
#pragma unroll
    for (int jj = 0; jj < 8; ++jj) {
        const int j = jBase + tj * 8 + jj;
        const float bias = bih[j] + bhh[j];
        float4 v = make_float4(acc[jj][0] + bias, acc[jj][1] + bias,
                               acc[jj][2] + bias, acc[jj][3] + bias);
        *reinterpret_cast<float4*>(&xg_t[(size_t)j * Bn + tb * 4]) = v;
    }
}

// ---------------------------------------------------------------------------
// Kernel 2: persistent LSTM recurrence + ragged max-pool.
// h[512][64] staged per step via cp.async.bulk (4 x 32KB chunks, ONE
// instruction each from thread 0, mbarrier completion). xg[t+1] prefetched via
// 4 bulk segments on a double-buffered smem+mbarrier pair; the prefetch is
// SKIPPED on the last step so no async transaction outlives the CTA.
// Dot: thread=(hh,b), packed f32x2 gate pairs. One scoped grid barrier/step.
// Dynamic smem: sH[512*64] + sW[512*16] + sXg[2][16*64] = 168 KB
// ---------------------------------------------------------------------------
#define LSTM_SMEM ((Hn * Bn + Hn * 16 + 2 * 16 * Bn) * (int)sizeof(float))
#define H_CHUNK_BYTES (128 * Bn * 4)        // 32 KB
#define XG_BYTES      (4 * Bn * 4)          // 1 KB per gate segment

__global__ __launch_bounds__(NTHR, 1)
void lstm_kernel(const float* __restrict__ Whh,
                 const int*   __restrict__ length) {
    extern __shared__ float sm[];
    float* sH  = sm;                   // [k][b]           512*64
    float* sW  = sH + Hn * Bn;         // [k][hh*4+g]      512*16
    float* sXg = sW + Hn * 16;         // [2][g][h2][b]    2*16*64
    __shared__ unsigned long long mbarH[4];   // h chunk barriers
    __shared__ unsigned long long mbarX[2];   // xg ping-pong barriers

    const int tid  = threadIdx.x;
    const int p    = blockIdx.x;
    const int hrow = p * 4;

    const int hh = tid >> 6;           // local h index (0..3)
    const int b  = tid & 63;           // batch (0..63)

    if (tid == 0) {
#pragma unroll
        for (int c = 0; c < 4; ++c) mbar_init(&mbarH[c], 1);
        mbar_init(&mbarX[0], 1);
        mbar_init(&mbarX[1], 1);
    }

    // Load this block's 16 W_hh rows: sW[k*16 + hh*4 + g], gate order i,f,g,o.
#pragma unroll
    for (int r = 0; r < 16; ++r) {
        const int g = r & 3, h2 = r >> 2;
        const float* src = Whh + (size_t)(g * Hn + hrow + h2) * Hn;
        for (int k = tid; k < Hn; k += NTHR)
            sW[k * 16 + h2 * 4 + g] = src[k];
    }
    // Zero this block's rows of h buffer 0 (fresh state every launch/replay).
    for (int i = tid; i < 4 * Bn; i += NTHR)
        g_h[0][hrow * Bn + i] = 0.f;
    __syncthreads();    // mbar init + sW visible before any bulk traffic

    // Prefetch xg slice for t=0 on mbarX[0]: all 4 gate segments (1 KB each).
    if (tid == 0) {
        fence_proxy_async_f();
        mbar_expect_tx(&mbarX[0], 4 * XG_BYTES);
#pragma unroll
        for (int g = 0; g < 4; ++g)
            bulk_g2s(sXg + g * (4 * Bn),
                     g_xg + (size_t)(g * Hn + hrow) * Bn,
                     XG_BYTES, &mbarX[0]);
    }

    float c_state = 0.f;
    float maxv    = -FLT_MAX;
    const int mylen = length[b];

    grid_barrier();   // release covers the h-buffer zeroing

    for (int t = 0; t < Tn; ++t) {
        const float* hsrc = g_h[t & 1];
        float*       hdst = g_h[(t + 1) & 1];
        const float* xgCur = sXg + (t & 1) * (16 * Bn);
        float*       xgNxt = sXg + ((t + 1) & 1) * (16 * Bn);

        // Issue all bulk copies for this step (thread 0 only, ~9 instructions).
        if (tid == 0) {
            fence_proxy_async_f();
#pragma unroll
            for (int c = 0; c < 4; ++c) {
                mbar_expect_tx(&mbarH[c], H_CHUNK_BYTES);
                bulk_g2s(sH + c * (128 * Bn), hsrc + c * (128 * Bn),
                         H_CHUNK_BYTES, &mbarH[c]);
            }
            if (t + 1 < Tn) {   // never leave an un-waited transaction at exit
                mbar_expect_tx(&mbarX[(t + 1) & 1], 4 * XG_BYTES);
#pragma unroll
                for (int g = 0; g < 4; ++g)
                    bulk_g2s(xgNxt + g * (4 * Bn),
                             g_xg + (size_t)(t + 1) * (G4 * Bn)
                                  + (size_t)(g * Hn + hrow) * Bn,
                             XG_BYTES, &mbarX[(t + 1) & 1]);
            }
        }

        unsigned long long acc_if = 0ull, acc_go = 0ull;   // {0f,0f} packed

        // xg[t] must be resident before the epilogue; wait up front (cheap).
        // mbarX[i] completes at steps with t&1==i; its phase flips every
        // other step -> parity = (t>>1)&1.
        mbar_wait_parity(&mbarX[t & 1], (unsigned)((t >> 1) & 1));

        // Pipelined dot: wait chunk c's mbarrier (parity t&1), then FFMA2.
#pragma unroll
        for (int c = 0; c < 4; ++c) {
            mbar_wait_parity(&mbarH[c], (unsigned)(t & 1));

            const float* pH = sH + c * (128 * Bn) + b;
            const float* pW = sW + c * (128 * 16) + hh * 4;
#pragma unroll 8
            for (int k = 0; k < 128; ++k) {
                const float hk = pH[k * Bn];                        // coalesced
                unsigned long long hkk;
                asm("mov.b64 %0, {%1, %1};" : "=l"(hkk) : "f"(hk)); // {hk,hk}
                const ulonglong2 w =
                    *reinterpret_cast<const ulonglong2*>(pW + k * 16); // bcast
                acc_if = ffma2(w.x, hkk, acc_if);   // {i,f}
                acc_go = ffma2(w.y, hkk, acc_go);   // {g,o}
            }
        }

        // Epilogue: fully register-local. xg smem layout: [g][h2][b].
        {
            float ai, af, ag, ao;
            asm("mov.b64 {%0, %1}, %2;" : "=f"(ai), "=f"(af) : "l"(acc_if));
            asm("mov.b64 {%0, %1}, %2;" : "=f"(ag), "=f"(ao) : "l"(acc_go));
            const float gi = xgCur[(0 * 4 + hh) * 64 + b] + ai;
            const float gf = xgCur[(1 * 4 + hh) * 64 + b] + af;
            const float gg = xgCur[(2 * 4 + hh) * 64 + b] + ag;
            const float go = xgCur[(3 * 4 + hh) * 64 + b] + ao;
            const float is = sigf(gi);
            const float fs = sigf(gf);
            const float gt = tanhf_fast(gg);
            const float os = sigf(go);
            c_state = fs * c_state + is * gt;
            const float h = os * tanhf_fast(c_state);
            hdst[(hrow + hh) * Bn + b] = h;
            if (t < mylen) maxv = fmaxf(maxv, h);
        }
        grid_barrier();   // release-arrive orders the h store
    }

    g_feat[(hrow + hh) * Bn + b] = maxv;
}

// ---------------------------------------------------------------------------
// Kernel 3: classifier  out[b][c] = sum_h feat[h][b] * W_cls[c][h] + b_cls[c]
// ---------------------------------------------------------------------------
__global__ void cls_kernel(const float* __restrict__ Wcls,
                           const float* __restrict__ bcls,
                           float* __restrict__ out) {
    const int tid = threadIdx.x;   // 128 threads
    const int b = tid >> 1, c = tid & 1;
    float s = bcls[c];
#pragma unroll 8
    for (int h = 0; h < Hn; ++h)
        s += g_feat[h * Bn + b] * Wcls[c * Hn + h];
    out[b * 2 + c] = s;
}

// ---------------------------------------------------------------------------
extern "C" void kernel_launch(void* const* d_in, const int* in_sizes, int n_in,
                              void* d_out, int out_size) {
    const int*   x      = (const int*)  d_in[0];  // [64,512] int32
    const int*   length = (const int*)  d_in[1];  // [64,1]   int32
    const float* emb    = (const float*)d_in[2];  // [32000,256]
    const float* Wih    = (const float*)d_in[3];  // [2048,256]
    const float* Whh    = (const float*)d_in[4];  // [2048,512]
    const float* bih    = (const float*)d_in[5];  // [2048]
    const float* bhh    = (const float*)d_in[6];  // [2048]
    const float* Wcls   = (const float*)d_in[7];  // [2,512]
    const float* bcls   = (const float*)d_in[8];  // [2]
    float* out = (float*)d_out;                   // [64,2]

    cudaFuncSetAttribute(lstm_kernel,
                         cudaFuncAttributeMaxDynamicSharedMemorySize, LSTM_SMEM);

    embed_gemm_kernel<<<dim3(16, Tn), 256>>>(x, emb, Wih, bih, bhh);
    lstm_kernel<<<NBLK, NTHR, LSTM_SMEM>>>(Whh, length);
    cls_kernel<<<1, 128>>>(Wcls, bcls, out);
    (void)in_sizes; (void)n_in; (void)out_size;
}